// round 1
// baseline (speedup 1.0000x reference)
#include <cuda_runtime.h>
#include <cstdint>
#include <math.h>

// Problem constants
#define N_NODES 8192
#define IN_C    128
#define OUT_C   16
// K hops = 3 adjacency matrices

// ---------------------------------------------------------------------------
// Scratch: support = X @ W + b   [8192 x 16]  (512 KB, __device__ global = legal scratch)
// ---------------------------------------------------------------------------
__device__ float g_support[N_NODES * OUT_C];

// ---------------------------------------------------------------------------
// Small helpers: packed f32x2 math (Blackwell PTX), cp.async, smem addr
// ---------------------------------------------------------------------------
__device__ __forceinline__ unsigned long long pack2(uint32_t a, uint32_t b) {
    unsigned long long r;
    asm("mov.b64 %0, {%1,%2};" : "=l"(r) : "r"(a), "r"(b));
    return r;
}
#define FMA_F32X2(d, a, b, c) \
    asm("fma.rn.f32x2 %0, %1, %2, %3;" : "=l"(d) : "l"(a), "l"(b), "l"(c))
#define ADD_F32X2(d, a, b) \
    asm("add.rn.f32x2 %0, %1, %2;" : "=l"(d) : "l"(a), "l"(b))
#define UNPACK_F32X2(lo, hi, v) \
    asm("mov.b64 {%0,%1}, %2;" : "=r"(lo), "=r"(hi) : "l"(v))

__device__ __forceinline__ uint32_t smem_u32(const void* p) {
    uint32_t a;
    asm("{ .reg .u64 t; cvta.to.shared.u64 t, %1; cvt.u32.u64 %0, t; }"
        : "=r"(a) : "l"(p));
    return a;
}
#define CP_ASYNC16(dst, src) \
    asm volatile("cp.async.cg.shared.global [%0], [%1], 16;" :: "r"(dst), "l"(src))
#define CP_COMMIT()  asm volatile("cp.async.commit_group;")
#define CP_WAIT1()   asm volatile("cp.async.wait_group 1;" ::: "memory")
#define CP_WAIT0()   asm volatile("cp.async.wait_group 0;" ::: "memory")

// ---------------------------------------------------------------------------
// Kernel 1: support[m][d] = sum_c x[m][c]*w[c][d] + b[d]
// grid = 512 blocks * 256 threads; thread -> (m = blk*16 + tid/16, d = tid%16)
// ---------------------------------------------------------------------------
__global__ void __launch_bounds__(256) support_kernel(
    const float* __restrict__ x, const float* __restrict__ w,
    const float* __restrict__ b)
{
    __shared__ float ws[IN_C * OUT_C];   // 8 KB
    int t = threadIdx.x;
    #pragma unroll
    for (int i = t; i < IN_C * OUT_C; i += 256) ws[i] = w[i];
    __syncthreads();

    int d = t & 15;
    int m = blockIdx.x * 16 + (t >> 4);
    float acc = b[d];
    const float4* xr = (const float4*)(x + (long)m * IN_C);
    #pragma unroll
    for (int c4 = 0; c4 < IN_C / 4; c4++) {
        float4 xv = xr[c4];
        int c = c4 * 4;
        acc = fmaf(xv.x, ws[(c + 0) * 16 + d], acc);
        acc = fmaf(xv.y, ws[(c + 1) * 16 + d], acc);
        acc = fmaf(xv.z, ws[(c + 2) * 16 + d], acc);
        acc = fmaf(xv.w, ws[(c + 3) * 16 + d], acc);
    }
    g_support[m * OUT_C + d] = acc;
}

// ---------------------------------------------------------------------------
// Kernel 2: out[n][d] = sum_m (att0*adj0 + att1*adj1 + att2*adj2)[n][m] * S[m][d]
//
// Block: 256 threads (8 warps), 32 rows. Warp owns 4 rows; lanes partition m.
// m-tile = 64, double-buffered in smem via cp.async.
// smem per buffer: adj 3*32*64 fp32 (24 KB) + support 64 rows * 20 fp32 (5 KB)
// (support stride 20 floats => conflict-free LDS.128 across lanes)
// ---------------------------------------------------------------------------
#define MT          64
#define ROWS        32
#define SUP_STRIDE  20
#define ADJ_FLOATS  (3 * ROWS * MT)            // 6144
#define SUP_FLOATS  (MT * SUP_STRIDE)          // 1280
#define BUF_FLOATS  (ADJ_FLOATS + SUP_FLOATS)  // 7424
#define SMEM_BYTES  (2 * BUF_FLOATS * 4)       // 59392

__device__ __forceinline__ void issue_tile(
    float* buf, const float* __restrict__ adj, int n0, int tile, int tid)
{
    uint32_t adj_dst = smem_u32(buf);
    uint32_t sup_dst = smem_u32(buf + ADJ_FLOATS);
    long t0 = (long)tile * MT;
    // adj: 3 * 32 rows * 16 chunks(16B) = 1536 chunks -> 6 per thread
    #pragma unroll
    for (int i = 0; i < 6; i++) {
        int c   = tid + i * 256;
        int k   = c >> 9;        // /512
        int rem = c & 511;
        int r   = rem >> 4;      // row 0..31
        int j   = rem & 15;      // 16B chunk within 64-float segment
        const float* src = adj + (long)k * N_NODES * N_NODES
                               + (long)(n0 + r) * N_NODES + t0 + j * 4;
        CP_ASYNC16(adj_dst + (uint32_t)((k * (ROWS * MT) + r * MT + j * 4) * 4), src);
    }
    // support: 64 rows * 4 chunks = 256 -> 1 per thread (strided dst, pad 20)
    {
        int m = tid >> 2;
        int j = tid & 3;
        const float* src = g_support + (t0 + m) * OUT_C + j * 4;
        CP_ASYNC16(sup_dst + (uint32_t)((m * SUP_STRIDE + j * 4) * 4), src);
    }
    CP_COMMIT();
}

__global__ void __launch_bounds__(256, 2) gcn_main_kernel(
    const float* __restrict__ adj, const float* __restrict__ attp,
    float* __restrict__ out)
{
    extern __shared__ float sm[];
    const int NTILES = N_NODES / MT;   // 128
    int tid  = threadIdx.x;
    int warp = tid >> 5;
    int lane = tid & 31;
    int n0   = blockIdx.x * ROWS;

    // softmax over the 3 attention params (cheap, every thread)
    float p0 = __ldg(attp), p1 = __ldg(attp + 1), p2 = __ldg(attp + 2);
    float mx = fmaxf(p0, fmaxf(p1, p2));
    float e0 = expf(p0 - mx), e1 = expf(p1 - mx), e2 = expf(p2 - mx);
    float inv = 1.0f / (e0 + e1 + e2);
    float att0 = e0 * inv, att1 = e1 * inv, att2 = e2 * inv;

    unsigned long long acc[4][8];
    #pragma unroll
    for (int r = 0; r < 4; r++)
        #pragma unroll
        for (int j = 0; j < 8; j++) acc[r][j] = 0ull;

    issue_tile(sm, adj, n0, 0, tid);

    for (int t = 0; t < NTILES; t++) {
        if (t + 1 < NTILES) {
            issue_tile((t + 1) & 1 ? sm + BUF_FLOATS : sm, adj, n0, t + 1, tid);
            CP_WAIT1();
        } else {
            CP_WAIT0();
        }
        __syncthreads();

        const float* A = (t & 1) ? sm + BUF_FLOATS : sm;
        const float* S = A + ADJ_FLOATS;

        #pragma unroll
        for (int step = 0; step < MT / 32; step++) {
            int m = step * 32 + lane;
            const uint4* sp = (const uint4*)(S + m * SUP_STRIDE);
            uint4 q0 = sp[0], q1 = sp[1], q2 = sp[2], q3 = sp[3];
            unsigned long long p[8];
            p[0] = pack2(q0.x, q0.y);  p[1] = pack2(q0.z, q0.w);
            p[2] = pack2(q1.x, q1.y);  p[3] = pack2(q1.z, q1.w);
            p[4] = pack2(q2.x, q2.y);  p[5] = pack2(q2.z, q2.w);
            p[6] = pack2(q3.x, q3.y);  p[7] = pack2(q3.z, q3.w);
            #pragma unroll
            for (int r = 0; r < 4; r++) {
                int lr = warp * 4 + r;
                float a0 = A[             lr * MT + m];
                float a1 = A[ROWS * MT  + lr * MT + m];
                float a2 = A[2*ROWS*MT  + lr * MT + m];
                float a  = fmaf(att2, a2, fmaf(att1, a1, att0 * a0));
                unsigned long long aa =
                    pack2(__float_as_uint(a), __float_as_uint(a));
                #pragma unroll
                for (int j = 0; j < 8; j++)
                    FMA_F32X2(acc[r][j], aa, p[j], acc[r][j]);
            }
        }
        __syncthreads();
    }

    // warp-reduce across lanes (m-partition) and store 4 rows * 16 outputs
    #pragma unroll
    for (int r = 0; r < 4; r++) {
        #pragma unroll
        for (int j = 0; j < 8; j++) {
            unsigned long long v = acc[r][j];
            #pragma unroll
            for (int off = 16; off; off >>= 1) {
                unsigned long long o = __shfl_xor_sync(0xffffffffu, v, off);
                ADD_F32X2(v, v, o);
            }
            acc[r][j] = v;
        }
        if (lane == 0) {
            int row = n0 + warp * 4 + r;
            float2* o = (float2*)(out + (long)row * OUT_C);
            #pragma unroll
            for (int j = 0; j < 8; j++) {
                uint32_t lo, hi;
                UNPACK_F32X2(lo, hi, acc[r][j]);
                o[j] = make_float2(__uint_as_float(lo), __uint_as_float(hi));
            }
        }
    }
}

// ---------------------------------------------------------------------------
// Launch
// ---------------------------------------------------------------------------
extern "C" void kernel_launch(void* const* d_in, const int* in_sizes, int n_in,
                              void* d_out, int out_size)
{
    // Identify inputs by element count (all distinct): x, w, b, adj, att_param
    const float *x = nullptr, *w = nullptr, *b = nullptr,
                *adj = nullptr, *attp = nullptr;
    for (int i = 0; i < n_in; i++) {
        switch (in_sizes[i]) {
            case N_NODES * IN_C:            x    = (const float*)d_in[i]; break;
            case IN_C * OUT_C:              w    = (const float*)d_in[i]; break;
            case OUT_C:                     b    = (const float*)d_in[i]; break;
            case 3:                         attp = (const float*)d_in[i]; break;
            default:                        adj  = (const float*)d_in[i]; break; // 201326592
        }
    }

    support_kernel<<<N_NODES / 16, 256>>>(x, w, b);

    cudaFuncSetAttribute(gcn_main_kernel,
                         cudaFuncAttributeMaxDynamicSharedMemorySize, SMEM_BYTES);
    gcn_main_kernel<<<N_NODES / ROWS, 256, SMEM_BYTES>>>(adj, attp, (float*)d_out);
}

// round 2
// speedup vs baseline: 1.0192x; 1.0192x over previous
#include <cuda_runtime.h>
#include <cstdint>
#include <math.h>

// Problem constants
#define N_NODES 8192
#define IN_C    128
#define OUT_C   16
// K hops = 3 adjacency matrices

// ---------------------------------------------------------------------------
// Scratch: support = X @ W + b   [8192 x 16]  (512 KB, __device__ global)
// ---------------------------------------------------------------------------
__device__ float g_support[N_NODES * OUT_C];

// ---------------------------------------------------------------------------
// Helpers: packed f32x2 math (Blackwell PTX), cp.async, smem addr
// ---------------------------------------------------------------------------
__device__ __forceinline__ unsigned long long pack2(uint32_t a, uint32_t b) {
    unsigned long long r;
    asm("mov.b64 %0, {%1,%2};" : "=l"(r) : "r"(a), "r"(b));
    return r;
}
#define FMA_F32X2(d, a, b, c) \
    asm("fma.rn.f32x2 %0, %1, %2, %3;" : "=l"(d) : "l"(a), "l"(b), "l"(c))
#define ADD_F32X2(d, a, b) \
    asm("add.rn.f32x2 %0, %1, %2;" : "=l"(d) : "l"(a), "l"(b))
#define UNPACK_F32X2(lo, hi, v) \
    asm("mov.b64 {%0,%1}, %2;" : "=r"(lo), "=r"(hi) : "l"(v))

__device__ __forceinline__ uint32_t smem_u32(const void* p) {
    uint32_t a;
    asm("{ .reg .u64 t; cvta.to.shared.u64 t, %1; cvt.u32.u64 %0, t; }"
        : "=r"(a) : "l"(p));
    return a;
}
#define CP_ASYNC16(dst, src) \
    asm volatile("cp.async.cg.shared.global [%0], [%1], 16;" :: "r"(dst), "l"(src))
#define CP_COMMIT()  asm volatile("cp.async.commit_group;")
#define CP_WAIT1()   asm volatile("cp.async.wait_group 1;" ::: "memory")
#define CP_WAIT0()   asm volatile("cp.async.wait_group 0;" ::: "memory")

// ---------------------------------------------------------------------------
// Kernel 1: support[m][d] = sum_c x[m][c]*w[c][d] + b[d]
// ---------------------------------------------------------------------------
__global__ void __launch_bounds__(256) support_kernel(
    const float* __restrict__ x, const float* __restrict__ w,
    const float* __restrict__ b)
{
    __shared__ float ws[IN_C * OUT_C];   // 8 KB
    int t = threadIdx.x;
    #pragma unroll
    for (int i = t; i < IN_C * OUT_C; i += 256) ws[i] = w[i];
    __syncthreads();

    int d = t & 15;
    int m = blockIdx.x * 16 + (t >> 4);
    float acc = b[d];
    const float4* xr = (const float4*)(x + (long)m * IN_C);
    #pragma unroll
    for (int c4 = 0; c4 < IN_C / 4; c4++) {
        float4 xv = xr[c4];
        int c = c4 * 4;
        acc = fmaf(xv.x, ws[(c + 0) * 16 + d], acc);
        acc = fmaf(xv.y, ws[(c + 1) * 16 + d], acc);
        acc = fmaf(xv.z, ws[(c + 2) * 16 + d], acc);
        acc = fmaf(xv.w, ws[(c + 3) * 16 + d], acc);
    }
    g_support[m * OUT_C + d] = acc;
}

// ---------------------------------------------------------------------------
// Kernel 2: out[n][d] = sum_m (att0*adj0 + att1*adj1 + att2*adj2)[n][m] * S[m][d]
//
// Block: 256 threads (8 warps), 32 rows. Warp owns 4 rows; lanes partition m.
// m-tile = 64, THREE-stage cp.async pipeline (2 groups in flight at all times).
// smem/stage: adj 3*32*64 fp32 (24 KB) + support 64*20 fp32 (5 KB) = 29 KB
// 3 stages = 89 KB/CTA, 2 CTAs/SM = 178 KB.
// ---------------------------------------------------------------------------
#define MT          64
#define ROWS        32
#define SUP_STRIDE  20
#define ADJ_FLOATS  (3 * ROWS * MT)            // 6144
#define SUP_FLOATS  (MT * SUP_STRIDE)          // 1280
#define BUF_FLOATS  (ADJ_FLOATS + SUP_FLOATS)  // 7424
#define STAGES      3
#define SMEM_BYTES  (STAGES * BUF_FLOATS * 4)  // 89088

__device__ __forceinline__ void issue_tile(
    float* buf, const float* __restrict__ adj, int n0, int tile, int tid)
{
    uint32_t adj_dst = smem_u32(buf);
    uint32_t sup_dst = smem_u32(buf + ADJ_FLOATS);
    long t0 = (long)tile * MT;
    // adj: 3 * 32 rows * 16 chunks(16B) = 1536 chunks -> 6 per thread
    #pragma unroll
    for (int i = 0; i < 6; i++) {
        int c   = tid + i * 256;
        int k   = c >> 9;        // /512
        int rem = c & 511;
        int r   = rem >> 4;      // row 0..31
        int j   = rem & 15;      // 16B chunk within 64-float segment
        const float* src = adj + (long)k * N_NODES * N_NODES
                               + (long)(n0 + r) * N_NODES + t0 + j * 4;
        CP_ASYNC16(adj_dst + (uint32_t)((k * (ROWS * MT) + r * MT + j * 4) * 4), src);
    }
    // support: 64 rows * 4 chunks = 256 -> 1 per thread (strided dst, pad 20)
    {
        int m = tid >> 2;
        int j = tid & 3;
        const float* src = g_support + (t0 + m) * OUT_C + j * 4;
        CP_ASYNC16(sup_dst + (uint32_t)((m * SUP_STRIDE + j * 4) * 4), src);
    }
    CP_COMMIT();
}

__global__ void __launch_bounds__(256, 2) gcn_main_kernel(
    const float* __restrict__ adj, const float* __restrict__ attp,
    float* __restrict__ out)
{
    extern __shared__ float sm[];
    const int NTILES = N_NODES / MT;   // 128
    int tid  = threadIdx.x;
    int warp = tid >> 5;
    int lane = tid & 31;
    int n0   = blockIdx.x * ROWS;

    // softmax over the 3 attention params
    float p0 = __ldg(attp), p1 = __ldg(attp + 1), p2 = __ldg(attp + 2);
    float mx = fmaxf(p0, fmaxf(p1, p2));
    float e0 = expf(p0 - mx), e1 = expf(p1 - mx), e2 = expf(p2 - mx);
    float inv = 1.0f / (e0 + e1 + e2);
    float att0 = e0 * inv, att1 = e1 * inv, att2 = e2 * inv;

    unsigned long long acc[4][8];
    #pragma unroll
    for (int r = 0; r < 4; r++)
        #pragma unroll
        for (int j = 0; j < 8; j++) acc[r][j] = 0ull;

    // Prologue: fill stages 0 and 1
    issue_tile(sm,              adj, n0, 0, tid);
    issue_tile(sm + BUF_FLOATS, adj, n0, 1, tid);

    int buf_idx = 0;
    for (int t = 0; t < NTILES; t++) {
        // Ensure group t complete. Pending = {t .. min(t+1, NT-1)}.
        if (t + 1 < NTILES) { CP_WAIT1(); } else { CP_WAIT0(); }
        __syncthreads();   // cp.async data visible to all; prev-iter reads done

        // Issue tile t+2 into the stage consumed at iteration t-1 (safe now)
        if (t + 2 < NTILES) {
            int nb = buf_idx + 2; if (nb >= STAGES) nb -= STAGES;
            issue_tile(sm + nb * BUF_FLOATS, adj, n0, t + 2, tid);
        }

        const float* A = sm + buf_idx * BUF_FLOATS;
        const float* S = A + ADJ_FLOATS;

        #pragma unroll
        for (int step = 0; step < MT / 32; step++) {
            int m = step * 32 + lane;
            const uint4* sp = (const uint4*)(S + m * SUP_STRIDE);
            uint4 q0 = sp[0], q1 = sp[1], q2 = sp[2], q3 = sp[3];
            unsigned long long p[8];
            p[0] = pack2(q0.x, q0.y);  p[1] = pack2(q0.z, q0.w);
            p[2] = pack2(q1.x, q1.y);  p[3] = pack2(q1.z, q1.w);
            p[4] = pack2(q2.x, q2.y);  p[5] = pack2(q2.z, q2.w);
            p[6] = pack2(q3.x, q3.y);  p[7] = pack2(q3.z, q3.w);
            #pragma unroll
            for (int r = 0; r < 4; r++) {
                int lr = warp * 4 + r;
                float a0 = A[             lr * MT + m];
                float a1 = A[ROWS * MT  + lr * MT + m];
                float a2 = A[2*ROWS*MT  + lr * MT + m];
                float a  = fmaf(att2, a2, fmaf(att1, a1, att0 * a0));
                unsigned long long aa =
                    pack2(__float_as_uint(a), __float_as_uint(a));
                #pragma unroll
                for (int j = 0; j < 8; j++)
                    FMA_F32X2(acc[r][j], aa, p[j], acc[r][j]);
            }
        }

        buf_idx++; if (buf_idx >= STAGES) buf_idx -= STAGES;
    }

    // warp-reduce across lanes (m-partition) and store 4 rows * 16 outputs
    #pragma unroll
    for (int r = 0; r < 4; r++) {
        #pragma unroll
        for (int j = 0; j < 8; j++) {
            unsigned long long v = acc[r][j];
            #pragma unroll
            for (int off = 16; off; off >>= 1) {
                unsigned long long o = __shfl_xor_sync(0xffffffffu, v, off);
                ADD_F32X2(v, v, o);
            }
            acc[r][j] = v;
        }
        if (lane == 0) {
            int row = n0 + warp * 4 + r;
            float2* o = (float2*)(out + (long)row * OUT_C);
            #pragma unroll
            for (int j = 0; j < 8; j++) {
                uint32_t lo, hi;
                UNPACK_F32X2(lo, hi, acc[r][j]);
                o[j] = make_float2(__uint_as_float(lo), __uint_as_float(hi));
            }
        }
    }
}

// ---------------------------------------------------------------------------
// Launch
// ---------------------------------------------------------------------------
extern "C" void kernel_launch(void* const* d_in, const int* in_sizes, int n_in,
                              void* d_out, int out_size)
{
    const float *x = nullptr, *w = nullptr, *b = nullptr,
                *adj = nullptr, *attp = nullptr;
    for (int i = 0; i < n_in; i++) {
        switch (in_sizes[i]) {
            case N_NODES * IN_C: x    = (const float*)d_in[i]; break;
            case IN_C * OUT_C:   w    = (const float*)d_in[i]; break;
            case OUT_C:          b    = (const float*)d_in[i]; break;
            case 3:              attp = (const float*)d_in[i]; break;
            default:             adj  = (const float*)d_in[i]; break; // 3*8192*8192
        }
    }

    support_kernel<<<N_NODES / 16, 256>>>(x, w, b);

    cudaFuncSetAttribute(gcn_main_kernel,
                         cudaFuncAttributeMaxDynamicSharedMemorySize, SMEM_BYTES);
    gcn_main_kernel<<<N_NODES / ROWS, 256, SMEM_BYTES>>>(adj, attp, (float*)d_out);
}